// round 9
// baseline (speedup 1.0000x reference)
#include <cuda_runtime.h>
#include <cstdint>

// Problem constants
#define N_TOTAL 16384   // 16 * 32 * 32 query vectors
#define KD      256     // embedding dim
#define KN      8192    // number of codebook entries
#define BATCH   16
#define HW      1024    // 32*32

// argmin-GEMM tiling
#define TN      128     // query rows per CTA
#define TK      64      // codebook rows per k-tile
#define XPITCH  128     // XsT row pitch (floats), d-major [KD][TN]
#define EPITCH  64      // EsT row pitch (floats), d-major [KD][TK], XOR-swizzled

#define ARG_SMEM_BYTES ((KD * XPITCH + KD * EPITCH) * 4)   // 196608 B

__device__ float g_esq[KN];
__device__ int   g_idx[N_TOTAL];

// ---- packed f32x2 helpers (sm_103a FFMA2 path) ----
__device__ __forceinline__ unsigned long long pack_dup(float v) {
    unsigned long long r;
    asm("mov.b64 %0, {%1, %1};" : "=l"(r) : "f"(v));
    return r;
}
__device__ __forceinline__ void fma2(unsigned long long& d,
                                     unsigned long long a,
                                     unsigned long long b) {
    asm("fma.rn.f32x2 %0, %1, %2, %0;" : "+l"(d) : "l"(a), "l"(b));
}
__device__ __forceinline__ void unpack2(unsigned long long v, float& lo, float& hi) {
    asm("mov.b64 {%0, %1}, %2;" : "=f"(lo), "=f"(hi) : "l"(v));
}

// ---------------------------------------------------------------------------
// e_sq[k] = sum_d emb[k][d]^2   (one warp per codebook row)
// ---------------------------------------------------------------------------
__global__ void esq_kernel(const float* __restrict__ emb) {
    int warp = threadIdx.x >> 5;
    int lane = threadIdx.x & 31;
    int k = blockIdx.x * 8 + warp;
    if (k >= KN) return;
    const float4* row = (const float4*)(emb + (size_t)k * KD);
    float s = 0.f;
    #pragma unroll
    for (int i = lane; i < KD / 4; i += 32) {
        float4 v = row[i];
        s += v.x * v.x + v.y * v.y + v.z * v.z + v.w * v.w;
    }
    #pragma unroll
    for (int o = 16; o; o >>= 1) s += __shfl_down_sync(0xffffffffu, s, o);
    if (lane == 0) g_esq[k] = s;
}

// ---------------------------------------------------------------------------
// Fused GEMM + argmin:  idx[n] = argmin_k ( e_sq[k] - 2 * <x_n, e_k> )
// (x_sq dropped: row-constant, order-preserving.)
//
// Smem (d-major):
//   XsT[d][r]   pitch 128 : xv = 2x LDS.128 broadcast (conflict-free)
//   EsT[d][.]   pitch 64, XOR-swizzled: physical float4 slot
//               p4 = col4 ^ ((d>>2)&7)  -> STS and LDS both conflict-free.
// E tiles are register-prefetched (software pipeline) across the k loop.
// Inner product in packed fma.rn.f32x2 (FFMA2): acc pairs adjacent query
// rows, which come straight out of LDS.128 as 64-bit halves (no pack cost).
// ---------------------------------------------------------------------------
extern "C" __global__ void __launch_bounds__(256, 1)
argmin_kernel(const float* __restrict__ z, const float* __restrict__ emb) {
    extern __shared__ float sm[];
    float* XsT = sm;                  // [KD][XPITCH]
    float* EsT = sm + KD * XPITCH;    // [KD][EPITCH] (swizzled)

    const int tid = threadIdx.x;
    const int tx  = tid & 15;         // codebook-column group (4 cols each)
    const int ty  = tid >> 4;         // query-row group (8 rows each)

    const int n0  = blockIdx.x * TN;
    const int b   = n0 >> 10;
    const int hw0 = n0 & 1023;

    // ---- Load X tile: XsT[d][r] = z[b][d][hw0+r], float4 both sides ----
    {
        const float4* zb4 = (const float4*)(z + (size_t)b * KD * HW + hw0);
        float4* xs4 = (float4*)XsT;
        #pragma unroll
        for (int m = tid; m < KD * (TN / 4); m += 256) {
            int d  = m >> 5;
            int r4 = m & 31;
            xs4[d * (XPITCH / 4) + r4] = zb4[(size_t)d * (HW / 4) + r4];
        }
    }

    // E-tile gmem mapping (constant per thread):
    //   dv      = (tid&7) + 8*(tid>>5)   float4 index along d (0..63)
    //   kk_base = (tid>>3)&3             codebook row mod 4
    // Thread's element it (0..15): E row kk = kk_base + 4*it, d-chunk dv.
    const int dv      = (tid & 7) + 8 * (tid >> 5);
    const int kk_base = (tid >> 3) & 3;
    const int fsw     = dv & 7;       // swizzle key for this thread's rows
    const float4* emb4 = (const float4*)emb;

    // Preload tile 0
    float4 pre[16];
    #pragma unroll
    for (int it = 0; it < 16; ++it)
        pre[it] = emb4[(size_t)(kk_base + 4 * it) * (KD / 4) + dv];
    __syncthreads();
    #pragma unroll
    for (int it = 0; it < 16; ++it) {
        float* dst = EsT + (size_t)(4 * dv) * EPITCH + 4 * (it ^ fsw) + kk_base;
        dst[0 * EPITCH] = pre[it].x;
        dst[1 * EPITCH] = pre[it].y;
        dst[2 * EPITCH] = pre[it].z;
        dst[3 * EPITCH] = pre[it].w;
    }
    __syncthreads();

    float rmin[8];
    int   ridx[8];
    #pragma unroll
    for (int i = 0; i < 8; i++) { rmin[i] = 3.4e38f; ridx[i] = 0; }

    const float* xp = XsT + ty * 8;

    for (int kt = 0; kt < KN / TK; ++kt) {
        const int k0 = kt * TK;

        // Prefetch next E tile into registers (overlaps with compute below)
        if (kt + 1 < KN / TK) {
            const float4* src = emb4 + (size_t)(k0 + TK) * (KD / 4);
            #pragma unroll
            for (int it = 0; it < 16; ++it)
                pre[it] = src[(size_t)(kk_base + 4 * it) * (KD / 4) + dv];
        }

        unsigned long long acc2[4][4];
        #pragma unroll
        for (int i2 = 0; i2 < 4; i2++)
            #pragma unroll
            for (int j = 0; j < 4; j++) acc2[i2][j] = 0ULL;

        #pragma unroll 4
        for (int d = 0; d < KD; ++d) {
            ulonglong2 xa2 = *(const ulonglong2*)(xp + (size_t)d * XPITCH);
            ulonglong2 xb2 = *(const ulonglong2*)(xp + (size_t)d * XPITCH + 4);
            // swizzled E read: physical slot p4 = tx ^ ((d>>2)&7)
            float4 ev = *(const float4*)(EsT + (size_t)d * EPITCH
                                             + 4 * (tx ^ ((d >> 2) & 7)));
            unsigned long long xr[4] = {xa2.x, xa2.y, xb2.x, xb2.y};
            unsigned long long ed[4] = {pack_dup(ev.x), pack_dup(ev.y),
                                        pack_dup(ev.z), pack_dup(ev.w)};
            #pragma unroll
            for (int i2 = 0; i2 < 4; i2++)
                #pragma unroll
                for (int j = 0; j < 4; j++)
                    fma2(acc2[i2][j], xr[i2], ed[j]);
        }

        // Running argmin. j ascending => k ascending per thread; strict '<'
        // keeps the earliest index (matches jnp.argmin tie-breaking).
        {
            float4 eqv = *(const float4*)(g_esq + k0 + 4 * tx);
            float eq[4] = {eqv.x, eqv.y, eqv.z, eqv.w};
            #pragma unroll
            for (int j = 0; j < 4; j++) {
                int k = k0 + 4 * tx + j;
                #pragma unroll
                for (int i2 = 0; i2 < 4; i2++) {
                    float alo, ahi;
                    unpack2(acc2[i2][j], alo, ahi);
                    float vlo = fmaf(-2.f, alo, eq[j]);
                    float vhi = fmaf(-2.f, ahi, eq[j]);
                    int ilo = 2 * i2, ihi = 2 * i2 + 1;
                    if (vlo < rmin[ilo]) { rmin[ilo] = vlo; ridx[ilo] = k; }
                    if (vhi < rmin[ihi]) { rmin[ihi] = vhi; ridx[ihi] = k; }
                }
            }
        }

        // Publish prefetched tile (conflict-free swizzled STS)
        __syncthreads();
        if (kt + 1 < KN / TK) {
            #pragma unroll
            for (int it = 0; it < 16; ++it) {
                float* dst = EsT + (size_t)(4 * dv) * EPITCH + 4 * (it ^ fsw) + kk_base;
                dst[0 * EPITCH] = pre[it].x;
                dst[1 * EPITCH] = pre[it].y;
                dst[2 * EPITCH] = pre[it].z;
                dst[3 * EPITCH] = pre[it].w;
            }
        }
        __syncthreads();
    }

    // Cross-thread (tx) reduction per row; smaller index wins ties.
    float* vs = sm;                       // [TN][16]
    int*   is = (int*)(sm + TN * 16);     // [TN][16]
    #pragma unroll
    for (int i = 0; i < 8; i++) {
        int r = ty * 8 + i;
        vs[r * 16 + tx] = rmin[i];
        is[r * 16 + tx] = ridx[i];
    }
    __syncthreads();
    for (int r = tid; r < TN; r += 256) {
        float bv = vs[r * 16];
        int   bi = is[r * 16];
        #pragma unroll
        for (int t = 1; t < 16; ++t) {
            float v = vs[r * 16 + t];
            int  id = is[r * 16 + t];
            if (v < bv || (v == bv && id < bi)) { bv = v; bi = id; }
        }
        g_idx[n0 + r] = bi;
    }
}

// ---------------------------------------------------------------------------
// Batched 32x32 tiled transpose: per-batch plane (R x C) -> (C x R).
// ---------------------------------------------------------------------------
__global__ void transpose_kernel(const float* __restrict__ in,
                                 float* __restrict__ out, int R, int C) {
    __shared__ float tile[32][33];
    const int bz = blockIdx.z;
    const float* ip = in  + (size_t)bz * R * C;
    float*       op = out + (size_t)bz * R * C;
    int c0 = blockIdx.x * 32;
    int r0 = blockIdx.y * 32;
    int tx = threadIdx.x, ty = threadIdx.y;   // 32 x 8
    #pragma unroll
    for (int k = 0; k < 32; k += 8)
        tile[ty + k][tx] = ip[(size_t)(r0 + ty + k) * C + c0 + tx];
    __syncthreads();
    #pragma unroll
    for (int k = 0; k < 32; k += 8)
        op[(size_t)(c0 + ty + k) * R + r0 + tx] = tile[tx][ty + k];
}

// ---------------------------------------------------------------------------
// quantized_flat[n] = emb[idx[n]], plus float index output.
// ---------------------------------------------------------------------------
__global__ void gather_kernel(const float* __restrict__ emb,
                              float* __restrict__ qf,
                              float* __restrict__ idxf) {
    int t = threadIdx.x;
    int n = blockIdx.x * 4 + (t >> 6);
    int c4 = t & 63;
    int id = g_idx[n];
    const float4* e = (const float4*)(emb + (size_t)id * KD);
    ((float4*)(qf + (size_t)n * KD))[c4] = e[c4];
    if (c4 == 0) idxf[n] = (float)id;
}

// ---------------------------------------------------------------------------
extern "C" void kernel_launch(void* const* d_in, const int* in_sizes, int n_in,
                              void* d_out, int out_size) {
    const float* z   = (const float*)d_in[0];   // (16, 256, 32, 32)
    const float* emb = (const float*)d_in[1];   // (8192, 256)
    float* out = (float*)d_out;

    float* enc   = out;                                   // encoded_flat  (N, 256)
    float* qf    = out + (size_t)N_TOTAL * KD;            // quantized_flat(N, 256)
    float* idxf  = out + (size_t)2 * N_TOTAL * KD;        // indices       (N,)
    float* quant = idxf + N_TOTAL;                        // quantized NCHW

    cudaFuncSetAttribute(argmin_kernel,
                         cudaFuncAttributeMaxDynamicSharedMemorySize,
                         ARG_SMEM_BYTES);

    esq_kernel<<<KN / 8, 256>>>(emb);
    argmin_kernel<<<N_TOTAL / TN, 256, ARG_SMEM_BYTES>>>(z, emb);
    // encoded_flat: per-batch plane (256 x 1024) -> (1024 x 256)
    transpose_kernel<<<dim3(HW / 32, KD / 32, BATCH), dim3(32, 8)>>>(z, enc, KD, HW);
    gather_kernel<<<N_TOTAL / 4, 256>>>(emb, qf, idxf);
    // quantized NCHW: per-batch plane (1024 x 256) -> (256 x 1024)
    transpose_kernel<<<dim3(KD / 32, HW / 32, BATCH), dim3(32, 8)>>>(qf, quant, HW, KD);
}

// round 15
// speedup vs baseline: 1.3675x; 1.3675x over previous
#include <cuda_runtime.h>
#include <cuda_bf16.h>
#include <cstdint>

// Problem constants
#define N_TOTAL 16384   // 16 * 32 * 32 query vectors
#define KD      256     // embedding dim
#define KN      8192    // number of codebook entries
#define BATCH   16
#define HW      1024    // 32*32

// mma argmin tiling
#define QT      128     // queries per CTA
#define NT      32      // codebook rows per tile
#define NTILES  (KN / NT)      // 256
#define MAXFLAG 512
#define DELTA   0.02f

// dynamic smem layout (bytes)
//  E: 2 buffers x (EHI 16K + ELO 16K) ; each split: [kblk4][n32][128B swizzled]
//  X staging: [kblk4][m128][128B swizzled] per split
#define SM_E      0
#define SM_XHI    65536
#define SM_XLO    131072
#define SM_ESQ    196608              // float[2][32]
#define SMEM_MMA  (196608 + 256)

__device__ float              g_esq[KN];
__device__ int                g_idx[N_TOTAL];
__device__ __nv_bfloat16      g_ehi[(size_t)KN * KD];
__device__ __nv_bfloat16      g_elo[(size_t)KN * KD];
__device__ int                g_nflag;
__device__ int                g_flagrow[MAXFLAG];
__device__ unsigned long long g_key[N_TOTAL];

// ---- PTX helpers (all compute_103-level features: sm_75/80 era) ----
__device__ __forceinline__ uint32_t smem_u32(const void* p) {
    uint32_t a;
    asm("{ .reg .u64 t; cvta.to.shared.u64 t, %1; cvt.u32.u64 %0, t; }" : "=r"(a) : "l"(p));
    return a;
}
__device__ __forceinline__ void cp16(uint32_t dst, const void* src) {
    asm volatile("cp.async.cg.shared.global [%0], [%1], 16;" :: "r"(dst), "l"(src) : "memory");
}
__device__ __forceinline__ void cp_commit() { asm volatile("cp.async.commit_group;" ::: "memory"); }
__device__ __forceinline__ void cp_wait0()  { asm volatile("cp.async.wait_group 0;" ::: "memory"); }
__device__ __forceinline__ void ldsm4(uint32_t* r, uint32_t addr) {
    asm volatile("ldmatrix.sync.aligned.m8n8.x4.shared.b16 {%0,%1,%2,%3}, [%4];"
        : "=r"(r[0]), "=r"(r[1]), "=r"(r[2]), "=r"(r[3]) : "r"(addr));
}
__device__ __forceinline__ void mma16816(float* c, const uint32_t* a, uint32_t b0, uint32_t b1) {
    asm volatile("mma.sync.aligned.m16n8k16.row.col.f32.bf16.bf16.f32 "
        "{%0,%1,%2,%3}, {%4,%5,%6,%7}, {%8,%9}, {%0,%1,%2,%3};"
        : "+f"(c[0]), "+f"(c[1]), "+f"(c[2]), "+f"(c[3])
        : "r"(a[0]), "r"(a[1]), "r"(a[2]), "r"(a[3]), "r"(b0), "r"(b1));
}

#define UPD(V1, I1, V2, I2, v, k)                              \
    do {                                                       \
        if ((v) < (V1)) { V2 = V1; I2 = I1; V1 = (v); I1 = (k); } \
        else if ((v) < (V2)) { V2 = (v); I2 = (k); }           \
    } while (0)

// ---------------------------------------------------------------------------
// reset: flag counter + rescue keys
// ---------------------------------------------------------------------------
__global__ void reset_kernel() {
    int i = blockIdx.x * blockDim.x + threadIdx.x;
    if (i == 0) g_nflag = 0;
    if (i < N_TOTAL) g_key[i] = ~0ULL;
}

// ---------------------------------------------------------------------------
// prep: emb -> bf16 hi/lo split + e_sq. One warp per codebook row.
// ---------------------------------------------------------------------------
__global__ void prep_kernel(const float* __restrict__ emb) {
    int warp = threadIdx.x >> 5, lane = threadIdx.x & 31;
    int k = blockIdx.x * 8 + warp;
    if (k >= KN) return;
    const float4* row4 = (const float4*)(emb + (size_t)k * KD);
    float4 a = row4[lane * 2], b = row4[lane * 2 + 1];
    float v[8] = {a.x, a.y, a.z, a.w, b.x, b.y, b.z, b.w};
    uint32_t hp[4], lp[4];
    float s = 0.f;
    #pragma unroll
    for (int i = 0; i < 4; i++) {
        float v0 = v[2 * i], v1 = v[2 * i + 1];
        s += v0 * v0 + v1 * v1;
        __nv_bfloat16 h0 = __float2bfloat16(v0), h1 = __float2bfloat16(v1);
        __nv_bfloat16 l0 = __float2bfloat16(v0 - __bfloat162float(h0));
        __nv_bfloat16 l1 = __float2bfloat16(v1 - __bfloat162float(h1));
        hp[i] = (uint32_t)__bfloat16_as_ushort(h0) | ((uint32_t)__bfloat16_as_ushort(h1) << 16);
        lp[i] = (uint32_t)__bfloat16_as_ushort(l0) | ((uint32_t)__bfloat16_as_ushort(l1) << 16);
    }
    ((uint4*)(g_ehi + (size_t)k * KD))[lane] = make_uint4(hp[0], hp[1], hp[2], hp[3]);
    ((uint4*)(g_elo + (size_t)k * KD))[lane] = make_uint4(lp[0], lp[1], lp[2], lp[3]);
    #pragma unroll
    for (int o = 16; o; o >>= 1) s += __shfl_down_sync(0xffffffffu, s, o);
    if (lane == 0) g_esq[k] = s;
}

// ---------------------------------------------------------------------------
// mma.sync argmin: 3 bf16 MMAs (hh, hl, lh) per (m,n) tile. X fragments
// register-resident (constant over all tiles); E tiles cp.async
// double-buffered. Per-thread top-2 + quad-shfl merge; near-ties
// (gap < DELTA) flagged for exact full rescue. Warp w owns rows [16w,16w+16).
// ---------------------------------------------------------------------------
extern "C" __global__ void __launch_bounds__(256, 1)
argmin_wmma_kernel(const float* __restrict__ z) {
    extern __shared__ char smem[];
    const uint32_t sb = smem_u32(smem);
    const int tid  = threadIdx.x;
    const int wid  = tid >> 5;
    const int lane = tid & 31;
    const int n0   = blockIdx.x * QT;
    const int b    = n0 >> 10;
    const int hw0  = n0 & 1023;
    float* sesq = (float*)(smem + SM_ESQ);   // [2][32]

    // --- preload E tile 0 (both splits) + esq tile 0 ---
    #pragma unroll
    for (int q = 0; q < 4; q++) {
        int c  = tid + q * 256;
        int n  = c >> 5, ch = c & 31;
        uint32_t dst = (uint32_t)((ch >> 3) * 4096 + n * 128 + (((ch & 7) * 16) ^ ((n & 7) << 4)));
        cp16(sb + SM_E + dst,         g_ehi + (size_t)n * KD + ch * 8);
        cp16(sb + SM_E + 16384 + dst, g_elo + (size_t)n * KD + ch * 8);
    }
    cp_commit();
    if (tid >= 128 && tid < 160) sesq[tid - 128] = g_esq[tid - 128];

    // --- X staging: split hi/lo into swizzled K-blocked smem ---
    {
        const float* zb = z + (size_t)b * KD * HW + hw0;
        for (int m = tid; m < QT * KD; m += 256) {
            int r = m & 127, d = m >> 7;
            float val = zb[(size_t)d * HW + r];
            __nv_bfloat16 h = __float2bfloat16(val);
            __nv_bfloat16 l = __float2bfloat16(val - __bfloat162float(h));
            int c   = (d & 63) * 2;
            int off = (d >> 6) * 16384 + r * 128 + (c ^ ((r & 7) << 4));
            *(__nv_bfloat16*)(smem + SM_XHI + off) = h;
            *(__nv_bfloat16*)(smem + SM_XLO + off) = l;
        }
    }
    __syncthreads();

    // --- load A (X) fragments into registers: 16 k-steps x (hi,lo) ---
    uint32_t ah[16][4], al[16][4];
    {
        int row_a = wid * 16 + (lane & 15);
        int kcA   = (lane & 16) ? 16 : 0;
        int sxa   = (row_a & 7) << 4;
        uint32_t abase = sb + (uint32_t)(row_a * 128);
        #pragma unroll
        for (int s = 0; s < 16; s++) {
            uint32_t o = (uint32_t)((s >> 2) * 16384 + ((((s & 3) * 32) + kcA) ^ sxa));
            ldsm4(ah[s], abase + SM_XHI + o);
            ldsm4(al[s], abase + SM_XLO + o);
        }
    }

    // --- B (E) address precompute ---
    const int row_b = (lane & 7) + ((lane & 16) ? 8 : 0);
    const int kcB   = (lane & 8) ? 16 : 0;
    const int sxb   = (row_b & 7) << 4;
    const uint32_t bbase = sb + SM_E + (uint32_t)(row_b * 128);

    float acc[4][4];
    #pragma unroll
    for (int nt = 0; nt < 4; nt++)
        #pragma unroll
        for (int j = 0; j < 4; j++) acc[nt][j] = 0.f;

    float v1[2] = {3.4e38f, 3.4e38f}, v2[2] = {3.4e38f, 3.4e38f};
    int   i1[2] = {0, 0},             i2[2] = {0, 0};
    const int q2 = 2 * (lane & 3);

    for (int t = 0; t < NTILES; ++t) {
        const int cur = t & 1;
        cp_wait0();
        __syncthreads();

        // prefetch next tile (overlaps compute below)
        if (t + 1 < NTILES) {
            const size_t tb = (size_t)(t + 1) * NT * KD;
            const uint32_t ebuf = sb + SM_E + (uint32_t)(((t + 1) & 1) * 32768);
            #pragma unroll
            for (int q = 0; q < 4; q++) {
                int c  = tid + q * 256;
                int n  = c >> 5, ch = c & 31;
                uint32_t dst = (uint32_t)((ch >> 3) * 4096 + n * 128 + (((ch & 7) * 16) ^ ((n & 7) << 4)));
                cp16(ebuf + dst,         g_ehi + tb + (size_t)n * KD + ch * 8);
                cp16(ebuf + 16384 + dst, g_elo + tb + (size_t)n * KD + ch * 8);
            }
            if (tid >= 128 && tid < 160)
                sesq[(cur ^ 1) * 32 + (tid - 128)] = g_esq[(t + 1) * NT + (tid - 128)];
        }
        cp_commit();

        // 16 k-steps of 3-split MMA
        const uint32_t eb = bbase + (uint32_t)(cur * 32768);
        #pragma unroll
        for (int s = 0; s < 16; s++) {
            uint32_t a0 = eb + (uint32_t)((s >> 2) * 4096 + ((((s & 3) * 32) + kcB) ^ sxb));
            uint32_t bh0[4], bh1[4], bl0[4], bl1[4];
            ldsm4(bh0, a0);
            ldsm4(bh1, a0 + 2048);
            ldsm4(bl0, a0 + 16384);
            ldsm4(bl1, a0 + 16384 + 2048);
            mma16816(acc[0], ah[s], bh0[0], bh0[1]);
            mma16816(acc[0], ah[s], bl0[0], bl0[1]);
            mma16816(acc[0], al[s], bh0[0], bh0[1]);
            mma16816(acc[1], ah[s], bh0[2], bh0[3]);
            mma16816(acc[1], ah[s], bl0[2], bl0[3]);
            mma16816(acc[1], al[s], bh0[2], bh0[3]);
            mma16816(acc[2], ah[s], bh1[0], bh1[1]);
            mma16816(acc[2], ah[s], bl1[0], bl1[1]);
            mma16816(acc[2], al[s], bh1[0], bh1[1]);
            mma16816(acc[3], ah[s], bh1[2], bh1[3]);
            mma16816(acc[3], ah[s], bl1[2], bl1[3]);
            mma16816(acc[3], al[s], bh1[2], bh1[3]);
        }

        // epilogue: distances + top-2 (ascending k; strict '<' keeps earliest)
        {
            const float* se = sesq + cur * 32;
            const int kb = t * NT;
            #pragma unroll
            for (int nt = 0; nt < 4; nt++) {
                float2 eq = *(const float2*)(se + 8 * nt + q2);
                int k0 = kb + 8 * nt + q2;
                float va = fmaf(-2.f, acc[nt][0], eq.x);
                float vb = fmaf(-2.f, acc[nt][1], eq.y);
                float vc = fmaf(-2.f, acc[nt][2], eq.x);
                float vd = fmaf(-2.f, acc[nt][3], eq.y);
                UPD(v1[0], i1[0], v2[0], i2[0], va, k0);
                UPD(v1[0], i1[0], v2[0], i2[0], vb, k0 + 1);
                UPD(v1[1], i1[1], v2[1], i2[1], vc, k0);
                UPD(v1[1], i1[1], v2[1], i2[1], vd, k0 + 1);
                acc[nt][0] = 0.f; acc[nt][1] = 0.f; acc[nt][2] = 0.f; acc[nt][3] = 0.f;
            }
        }
    }

    // quad butterfly merge (lanes sharing a row: lane^1, lane^2)
    #pragma unroll
    for (int rr = 0; rr < 2; rr++) {
        #pragma unroll
        for (int d = 1; d < 4; d <<= 1) {
            float u1 = __shfl_xor_sync(0xffffffffu, v1[rr], d);
            int   j1 = __shfl_xor_sync(0xffffffffu, i1[rr], d);
            float u2 = __shfl_xor_sync(0xffffffffu, v2[rr], d);
            int   j2 = __shfl_xor_sync(0xffffffffu, i2[rr], d);
            if (u1 < v1[rr] || (u1 == v1[rr] && j1 < i1[rr])) {
                bool s2 = (v1[rr] < u2 || (v1[rr] == u2 && i1[rr] < j2));
                v2[rr] = s2 ? v1[rr] : u2;  i2[rr] = s2 ? i1[rr] : j2;
                v1[rr] = u1;  i1[rr] = j1;
            } else {
                bool s2 = (u1 < v2[rr] || (u1 == v2[rr] && j1 < i2[rr]));
                v2[rr] = s2 ? u1 : v2[rr];  i2[rr] = s2 ? j1 : i2[rr];
            }
        }
    }

    if ((lane & 3) == 0) {
        #pragma unroll
        for (int rr = 0; rr < 2; rr++) {
            int row = n0 + wid * 16 + (lane >> 2) + 8 * rr;
            g_idx[row] = i1[rr];
            if (v2[rr] - v1[rr] < DELTA) {
                int slot = atomicAdd(&g_nflag, 1);
                if (slot < MAXFLAG) g_flagrow[slot] = row;
            }
        }
    }
}

// ---------------------------------------------------------------------------
// rescue: EXACT fp32 argmin over ALL codes for flagged rows.
// 8 CTAs per flagged row (1024 codes each); combine via packed atomicMin.
// ---------------------------------------------------------------------------
__global__ void rescue_kernel(const float* __restrict__ z, const float* __restrict__ emb) {
    __shared__ float xs[KD];
    __shared__ unsigned long long keys[256];
    int nf = g_nflag;
    if (nf > MAXFLAG) nf = MAXFLAG;
    int slot = blockIdx.x >> 3;
    if (slot >= nf) return;
    int row = g_flagrow[slot];
    int b = row >> 10, hw = row & 1023;
    int tid = threadIdx.x;
    xs[tid] = z[(size_t)b * KD * HW + (size_t)tid * HW + hw];
    __syncthreads();
    int k0 = (blockIdx.x & 7) * 1024 + tid * 4;
    float bv = 3.4e38f; int bi = 0;
    for (int j = 0; j < 4; j++) {
        int k = k0 + j;
        const float* e = emb + (size_t)k * KD;
        float s = 0.f;
        #pragma unroll 8
        for (int d = 0; d < KD; d++) s = fmaf(xs[d], e[d], s);
        float v = fmaf(-2.f, s, g_esq[k]);
        if (v < bv) { bv = v; bi = k; }
    }
    uint32_t u = __float_as_uint(bv);
    u = (u & 0x80000000u) ? ~u : (u | 0x80000000u);
    keys[tid] = ((unsigned long long)u << 32) | (uint32_t)bi;
    __syncthreads();
    for (int off = 128; off; off >>= 1) {
        if (tid < off) {
            unsigned long long o = keys[tid + off];
            if (o < keys[tid]) keys[tid] = o;
        }
        __syncthreads();
    }
    if (tid == 0) atomicMin(&g_key[row], keys[0]);
}

__global__ void fixup_kernel() {
    int nf = g_nflag;
    if (nf > MAXFLAG) nf = MAXFLAG;
    int s = blockIdx.x * blockDim.x + threadIdx.x;
    if (s < nf) {
        int row = g_flagrow[s];
        g_idx[row] = (int)(g_key[row] & 0xffffffffu);
    }
}

// ---------------------------------------------------------------------------
// Batched 32x32 tiled transpose: per-batch plane (R x C) -> (C x R).
// ---------------------------------------------------------------------------
__global__ void transpose_kernel(const float* __restrict__ in,
                                 float* __restrict__ out, int R, int C) {
    __shared__ float tile[32][33];
    const int bz = blockIdx.z;
    const float* ip = in  + (size_t)bz * R * C;
    float*       op = out + (size_t)bz * R * C;
    int c0 = blockIdx.x * 32;
    int r0 = blockIdx.y * 32;
    int tx = threadIdx.x, ty = threadIdx.y;   // 32 x 8
    #pragma unroll
    for (int k = 0; k < 32; k += 8)
        tile[ty + k][tx] = ip[(size_t)(r0 + ty + k) * C + c0 + tx];
    __syncthreads();
    #pragma unroll
    for (int k = 0; k < 32; k += 8)
        op[(size_t)(c0 + ty + k) * R + r0 + tx] = tile[tx][ty + k];
}

// ---------------------------------------------------------------------------
// quantized_flat[n] = emb[idx[n]], plus float index output.
// ---------------------------------------------------------------------------
__global__ void gather_kernel(const float* __restrict__ emb,
                              float* __restrict__ qf,
                              float* __restrict__ idxf) {
    int t = threadIdx.x;
    int n = blockIdx.x * 4 + (t >> 6);
    int c4 = t & 63;
    int id = g_idx[n];
    const float4* e = (const float4*)(emb + (size_t)id * KD);
    ((float4*)(qf + (size_t)n * KD))[c4] = e[c4];
    if (c4 == 0) idxf[n] = (float)id;
}

// ---------------------------------------------------------------------------
extern "C" void kernel_launch(void* const* d_in, const int* in_sizes, int n_in,
                              void* d_out, int out_size) {
    const float* z   = (const float*)d_in[0];   // (16, 256, 32, 32)
    const float* emb = (const float*)d_in[1];   // (8192, 256)
    float* out = (float*)d_out;

    float* enc   = out;                                   // encoded_flat  (N, 256)
    float* qf    = out + (size_t)N_TOTAL * KD;            // quantized_flat(N, 256)
    float* idxf  = out + (size_t)2 * N_TOTAL * KD;        // indices       (N,)
    float* quant = idxf + N_TOTAL;                        // quantized NCHW

    cudaFuncSetAttribute(argmin_wmma_kernel,
                         cudaFuncAttributeMaxDynamicSharedMemorySize, SMEM_MMA);

    reset_kernel<<<64, 256>>>();
    prep_kernel<<<KN / 8, 256>>>(emb);
    argmin_wmma_kernel<<<N_TOTAL / QT, 256, SMEM_MMA>>>(z);
    rescue_kernel<<<MAXFLAG * 8, 256>>>(z, emb);
    fixup_kernel<<<2, 256>>>();
    // encoded_flat: per-batch plane (256 x 1024) -> (1024 x 256)
    transpose_kernel<<<dim3(HW / 32, KD / 32, BATCH), dim3(32, 8)>>>(z, enc, KD, HW);
    gather_kernel<<<N_TOTAL / 4, 256>>>(emb, qf, idxf);
    // quantized NCHW: per-batch plane (1024 x 256) -> (256 x 1024)
    transpose_kernel<<<dim3(KD / 32, HW / 32, BATCH), dim3(32, 8)>>>(qf, quant, HW, KD);
}

// round 16
// speedup vs baseline: 1.7262x; 1.2623x over previous
#include <cuda_runtime.h>
#include <cuda_bf16.h>
#include <cstdint>

// Problem constants
#define N_TOTAL 16384   // 16 * 32 * 32 query vectors
#define KD      256     // embedding dim
#define KN      8192    // number of codebook entries
#define BATCH   16
#define HW      1024    // 32*32

// mma argmin tiling
#define QT      128     // queries per CTA
#define NT      32      // codebook rows per tile
#define NTILES  (KN / NT)      // 256
#define MAXFLAG 4096
#define DELTA   0.02f

// dynamic smem layout (bytes)
#define SM_E      0
#define SM_XHI    65536
#define SM_XLO    131072
#define SM_ESQ    196608              // float[2][32]
#define SMEM_MMA  (196608 + 256)

__device__ float              g_esq[KN];
__device__ int                g_idx[N_TOTAL];
__device__ __nv_bfloat16      g_ehi[(size_t)KN * KD];
__device__ __nv_bfloat16      g_elo[(size_t)KN * KD];
__device__ int                g_nflag;
__device__ int                g_flagrow[MAXFLAG];

// ---- PTX helpers (all compute_103-level features: sm_75/80 era) ----
__device__ __forceinline__ uint32_t smem_u32(const void* p) {
    uint32_t a;
    asm("{ .reg .u64 t; cvta.to.shared.u64 t, %1; cvt.u32.u64 %0, t; }" : "=r"(a) : "l"(p));
    return a;
}
__device__ __forceinline__ void cp16(uint32_t dst, const void* src) {
    asm volatile("cp.async.cg.shared.global [%0], [%1], 16;" :: "r"(dst), "l"(src) : "memory");
}
__device__ __forceinline__ void cp_commit() { asm volatile("cp.async.commit_group;" ::: "memory"); }
__device__ __forceinline__ void cp_wait0()  { asm volatile("cp.async.wait_group 0;" ::: "memory"); }
__device__ __forceinline__ void ldsm4(uint32_t* r, uint32_t addr) {
    asm volatile("ldmatrix.sync.aligned.m8n8.x4.shared.b16 {%0,%1,%2,%3}, [%4];"
        : "=r"(r[0]), "=r"(r[1]), "=r"(r[2]), "=r"(r[3]) : "r"(addr));
}
__device__ __forceinline__ void mma16816(float* c, const uint32_t* a, uint32_t b0, uint32_t b1) {
    asm volatile("mma.sync.aligned.m16n8k16.row.col.f32.bf16.bf16.f32 "
        "{%0,%1,%2,%3}, {%4,%5,%6,%7}, {%8,%9}, {%0,%1,%2,%3};"
        : "+f"(c[0]), "+f"(c[1]), "+f"(c[2]), "+f"(c[3])
        : "r"(a[0]), "r"(a[1]), "r"(a[2]), "r"(a[3]), "r"(b0), "r"(b1));
}

#define UPD(V1, I1, V2, I2, v, k)                              \
    do {                                                       \
        if ((v) < (V1)) { V2 = V1; I2 = I1; V1 = (v); I1 = (k); } \
        else if ((v) < (V2)) { V2 = (v); I2 = (k); }           \
    } while (0)

// ---------------------------------------------------------------------------
// reset flag counter
// ---------------------------------------------------------------------------
__global__ void reset_kernel() { if (threadIdx.x == 0) g_nflag = 0; }

// ---------------------------------------------------------------------------
// prep: emb -> bf16 hi/lo split + e_sq. One warp per codebook row.
// ---------------------------------------------------------------------------
__global__ void prep_kernel(const float* __restrict__ emb) {
    int warp = threadIdx.x >> 5, lane = threadIdx.x & 31;
    int k = blockIdx.x * 8 + warp;
    if (k >= KN) return;
    const float4* row4 = (const float4*)(emb + (size_t)k * KD);
    float4 a = row4[lane * 2], b = row4[lane * 2 + 1];
    float v[8] = {a.x, a.y, a.z, a.w, b.x, b.y, b.z, b.w};
    uint32_t hp[4], lp[4];
    float s = 0.f;
    #pragma unroll
    for (int i = 0; i < 4; i++) {
        float v0 = v[2 * i], v1 = v[2 * i + 1];
        s += v0 * v0 + v1 * v1;
        __nv_bfloat16 h0 = __float2bfloat16(v0), h1 = __float2bfloat16(v1);
        __nv_bfloat16 l0 = __float2bfloat16(v0 - __bfloat162float(h0));
        __nv_bfloat16 l1 = __float2bfloat16(v1 - __bfloat162float(h1));
        hp[i] = (uint32_t)__bfloat16_as_ushort(h0) | ((uint32_t)__bfloat16_as_ushort(h1) << 16);
        lp[i] = (uint32_t)__bfloat16_as_ushort(l0) | ((uint32_t)__bfloat16_as_ushort(l1) << 16);
    }
    ((uint4*)(g_ehi + (size_t)k * KD))[lane] = make_uint4(hp[0], hp[1], hp[2], hp[3]);
    ((uint4*)(g_elo + (size_t)k * KD))[lane] = make_uint4(lp[0], lp[1], lp[2], lp[3]);
    #pragma unroll
    for (int o = 16; o; o >>= 1) s += __shfl_down_sync(0xffffffffu, s, o);
    if (lane == 0) g_esq[k] = s;
}

// ---------------------------------------------------------------------------
// mma.sync argmin: 3 bf16 MMAs (hh, hl, lh) per (m,n) tile. X fragments
// register-resident (constant over all tiles); E tiles cp.async
// double-buffered. Per-thread top-2 + quad-shfl merge; near-ties
// (gap < DELTA) flagged for exact full rescue. Warp w owns rows [16w,16w+16).
// ---------------------------------------------------------------------------
extern "C" __global__ void __launch_bounds__(256, 1)
argmin_wmma_kernel(const float* __restrict__ z) {
    extern __shared__ char smem[];
    const uint32_t sb = smem_u32(smem);
    const int tid  = threadIdx.x;
    const int wid  = tid >> 5;
    const int lane = tid & 31;
    const int n0   = blockIdx.x * QT;
    const int b    = n0 >> 10;
    const int hw0  = n0 & 1023;
    float* sesq = (float*)(smem + SM_ESQ);   // [2][32]

    // --- preload E tile 0 (both splits) + esq tile 0 ---
    #pragma unroll
    for (int q = 0; q < 4; q++) {
        int c  = tid + q * 256;
        int n  = c >> 5, ch = c & 31;
        uint32_t dst = (uint32_t)((ch >> 3) * 4096 + n * 128 + (((ch & 7) * 16) ^ ((n & 7) << 4)));
        cp16(sb + SM_E + dst,         g_ehi + (size_t)n * KD + ch * 8);
        cp16(sb + SM_E + 16384 + dst, g_elo + (size_t)n * KD + ch * 8);
    }
    cp_commit();
    if (tid >= 128 && tid < 160) sesq[tid - 128] = g_esq[tid - 128];

    // --- X staging: split hi/lo into swizzled K-blocked smem ---
    {
        const float* zb = z + (size_t)b * KD * HW + hw0;
        for (int m = tid; m < QT * KD; m += 256) {
            int r = m & 127, d = m >> 7;
            float val = zb[(size_t)d * HW + r];
            __nv_bfloat16 h = __float2bfloat16(val);
            __nv_bfloat16 l = __float2bfloat16(val - __bfloat162float(h));
            int c   = (d & 63) * 2;
            int off = (d >> 6) * 16384 + r * 128 + (c ^ ((r & 7) << 4));
            *(__nv_bfloat16*)(smem + SM_XHI + off) = h;
            *(__nv_bfloat16*)(smem + SM_XLO + off) = l;
        }
    }
    __syncthreads();

    // --- load A (X) fragments into registers: 16 k-steps x (hi,lo) ---
    uint32_t ah[16][4], al[16][4];
    {
        int row_a = wid * 16 + (lane & 15);
        int kcA   = (lane & 16) ? 16 : 0;
        int sxa   = (row_a & 7) << 4;
        uint32_t abase = sb + (uint32_t)(row_a * 128);
        #pragma unroll
        for (int s = 0; s < 16; s++) {
            uint32_t o = (uint32_t)((s >> 2) * 16384 + ((((s & 3) * 32) + kcA) ^ sxa));
            ldsm4(ah[s], abase + SM_XHI + o);
            ldsm4(al[s], abase + SM_XLO + o);
        }
    }

    // --- B (E) address precompute ---
    const int row_b = (lane & 7) + ((lane & 16) ? 8 : 0);
    const int kcB   = (lane & 8) ? 16 : 0;
    const int sxb   = (row_b & 7) << 4;
    const uint32_t bbase = sb + SM_E + (uint32_t)(row_b * 128);

    float acc[4][4];
    #pragma unroll
    for (int nt = 0; nt < 4; nt++)
        #pragma unroll
        for (int j = 0; j < 4; j++) acc[nt][j] = 0.f;

    float v1[2] = {3.4e38f, 3.4e38f}, v2[2] = {3.4e38f, 3.4e38f};
    int   i1[2] = {0, 0},             i2[2] = {0, 0};
    const int q2 = 2 * (lane & 3);

    for (int t = 0; t < NTILES; ++t) {
        const int cur = t & 1;
        cp_wait0();
        __syncthreads();

        // prefetch next tile (overlaps compute below)
        if (t + 1 < NTILES) {
            const size_t tb = (size_t)(t + 1) * NT * KD;
            const uint32_t ebuf = sb + SM_E + (uint32_t)(((t + 1) & 1) * 32768);
            #pragma unroll
            for (int q = 0; q < 4; q++) {
                int c  = tid + q * 256;
                int n  = c >> 5, ch = c & 31;
                uint32_t dst = (uint32_t)((ch >> 3) * 4096 + n * 128 + (((ch & 7) * 16) ^ ((n & 7) << 4)));
                cp16(ebuf + dst,         g_ehi + tb + (size_t)n * KD + ch * 8);
                cp16(ebuf + 16384 + dst, g_elo + tb + (size_t)n * KD + ch * 8);
            }
            if (tid >= 128 && tid < 160)
                sesq[(cur ^ 1) * 32 + (tid - 128)] = g_esq[(t + 1) * NT + (tid - 128)];
        }
        cp_commit();

        // 16 k-steps of 3-split MMA
        const uint32_t eb = bbase + (uint32_t)(cur * 32768);
        #pragma unroll
        for (int s = 0; s < 16; s++) {
            uint32_t a0 = eb + (uint32_t)((s >> 2) * 4096 + ((((s & 3) * 32) + kcB) ^ sxb));
            uint32_t bh0[4], bh1[4], bl0[4], bl1[4];
            ldsm4(bh0, a0);
            ldsm4(bh1, a0 + 2048);
            ldsm4(bl0, a0 + 16384);
            ldsm4(bl1, a0 + 16384 + 2048);
            mma16816(acc[0], ah[s], bh0[0], bh0[1]);
            mma16816(acc[0], ah[s], bl0[0], bl0[1]);
            mma16816(acc[0], al[s], bh0[0], bh0[1]);
            mma16816(acc[1], ah[s], bh0[2], bh0[3]);
            mma16816(acc[1], ah[s], bl0[2], bl0[3]);
            mma16816(acc[1], al[s], bh0[2], bh0[3]);
            mma16816(acc[2], ah[s], bh1[0], bh1[1]);
            mma16816(acc[2], ah[s], bl1[0], bl1[1]);
            mma16816(acc[2], al[s], bh1[0], bh1[1]);
            mma16816(acc[3], ah[s], bh1[2], bh1[3]);
            mma16816(acc[3], ah[s], bl1[2], bl1[3]);
            mma16816(acc[3], al[s], bh1[2], bh1[3]);
        }

        // epilogue: distances + top-2 (ascending k; strict '<' keeps earliest)
        {
            const float* se = sesq + cur * 32;
            const int kb = t * NT;
            #pragma unroll
            for (int nt = 0; nt < 4; nt++) {
                float2 eq = *(const float2*)(se + 8 * nt + q2);
                int k0 = kb + 8 * nt + q2;
                float va = fmaf(-2.f, acc[nt][0], eq.x);
                float vb = fmaf(-2.f, acc[nt][1], eq.y);
                float vc = fmaf(-2.f, acc[nt][2], eq.x);
                float vd = fmaf(-2.f, acc[nt][3], eq.y);
                UPD(v1[0], i1[0], v2[0], i2[0], va, k0);
                UPD(v1[0], i1[0], v2[0], i2[0], vb, k0 + 1);
                UPD(v1[1], i1[1], v2[1], i2[1], vc, k0);
                UPD(v1[1], i1[1], v2[1], i2[1], vd, k0 + 1);
                acc[nt][0] = 0.f; acc[nt][1] = 0.f; acc[nt][2] = 0.f; acc[nt][3] = 0.f;
            }
        }
    }

    // quad butterfly merge (lanes sharing a row: lane^1, lane^2)
    #pragma unroll
    for (int rr = 0; rr < 2; rr++) {
        #pragma unroll
        for (int d = 1; d < 4; d <<= 1) {
            float u1 = __shfl_xor_sync(0xffffffffu, v1[rr], d);
            int   j1 = __shfl_xor_sync(0xffffffffu, i1[rr], d);
            float u2 = __shfl_xor_sync(0xffffffffu, v2[rr], d);
            int   j2 = __shfl_xor_sync(0xffffffffu, i2[rr], d);
            if (u1 < v1[rr] || (u1 == v1[rr] && j1 < i1[rr])) {
                bool s2 = (v1[rr] < u2 || (v1[rr] == u2 && i1[rr] < j2));
                v2[rr] = s2 ? v1[rr] : u2;  i2[rr] = s2 ? i1[rr] : j2;
                v1[rr] = u1;  i1[rr] = j1;
            } else {
                bool s2 = (u1 < v2[rr] || (u1 == v2[rr] && j1 < i2[rr]));
                v2[rr] = s2 ? u1 : v2[rr];  i2[rr] = s2 ? j1 : i2[rr];
            }
        }
    }

    if ((lane & 3) == 0) {
        #pragma unroll
        for (int rr = 0; rr < 2; rr++) {
            int row = n0 + wid * 16 + (lane >> 2) + 8 * rr;
            g_idx[row] = i1[rr];
            if (v2[rr] - v1[rr] < DELTA) {
                int slot = atomicAdd(&g_nflag, 1);
                if (slot < MAXFLAG) g_flagrow[slot] = row;
            }
        }
    }
}

// ---------------------------------------------------------------------------
// rescue: EXACT fp32 argmin over ALL codes for flagged rows.
// One CTA per flagged row; each thread scans 32 codes (stride 256) with
// float4 loads and 4-way ILP partial sums; block-reduce packed keys.
// ---------------------------------------------------------------------------
__global__ void rescue_kernel(const float* __restrict__ z, const float* __restrict__ emb) {
    __shared__ float xs[KD];
    __shared__ unsigned long long keys[256];
    int nf = g_nflag;
    if (nf > MAXFLAG) nf = MAXFLAG;
    int slot = blockIdx.x;
    if (slot >= nf) return;
    int row = g_flagrow[slot];
    int b = row >> 10, hw = row & 1023;
    int tid = threadIdx.x;
    xs[tid] = z[(size_t)b * KD * HW + (size_t)tid * HW + hw];
    __syncthreads();
    float bv = 3.4e38f; int bi = 0;
    for (int k = tid; k < KN; k += 256) {
        const float4* e4 = (const float4*)(emb + (size_t)k * KD);
        float s0 = 0.f, s1 = 0.f, s2 = 0.f, s3 = 0.f;
        #pragma unroll 8
        for (int d4 = 0; d4 < KD / 4; d4++) {
            float4 ev = e4[d4];
            float4 xv = *(const float4*)(xs + d4 * 4);
            s0 = fmaf(xv.x, ev.x, s0);
            s1 = fmaf(xv.y, ev.y, s1);
            s2 = fmaf(xv.z, ev.z, s2);
            s3 = fmaf(xv.w, ev.w, s3);
        }
        float v = fmaf(-2.f, (s0 + s1) + (s2 + s3), g_esq[k]);
        if (v < bv) { bv = v; bi = k; }
    }
    // packed key: order-preserving float bits (high) | index (low)
    uint32_t u = __float_as_uint(bv);
    u = (u & 0x80000000u) ? ~u : (u | 0x80000000u);
    keys[tid] = ((unsigned long long)u << 32) | (uint32_t)bi;
    __syncthreads();
    for (int off = 128; off; off >>= 1) {
        if (tid < off) {
            unsigned long long o = keys[tid + off];
            if (o < keys[tid]) keys[tid] = o;
        }
        __syncthreads();
    }
    if (tid == 0) g_idx[row] = (int)(keys[0] & 0xffffffffu);
}

// ---------------------------------------------------------------------------
// Batched 32x32 tiled transpose: per-batch plane (R x C) -> (C x R).
// ---------------------------------------------------------------------------
__global__ void transpose_kernel(const float* __restrict__ in,
                                 float* __restrict__ out, int R, int C) {
    __shared__ float tile[32][33];
    const int bz = blockIdx.z;
    const float* ip = in  + (size_t)bz * R * C;
    float*       op = out + (size_t)bz * R * C;
    int c0 = blockIdx.x * 32;
    int r0 = blockIdx.y * 32;
    int tx = threadIdx.x, ty = threadIdx.y;   // 32 x 8
    #pragma unroll
    for (int k = 0; k < 32; k += 8)
        tile[ty + k][tx] = ip[(size_t)(r0 + ty + k) * C + c0 + tx];
    __syncthreads();
    #pragma unroll
    for (int k = 0; k < 32; k += 8)
        op[(size_t)(c0 + ty + k) * R + r0 + tx] = tile[tx][ty + k];
}

// ---------------------------------------------------------------------------
// quantized_flat[n] = emb[idx[n]], plus float index output.
// ---------------------------------------------------------------------------
__global__ void gather_kernel(const float* __restrict__ emb,
                              float* __restrict__ qf,
                              float* __restrict__ idxf) {
    int t = threadIdx.x;
    int n = blockIdx.x * 4 + (t >> 6);
    int c4 = t & 63;
    int id = g_idx[n];
    const float4* e = (const float4*)(emb + (size_t)id * KD);
    ((float4*)(qf + (size_t)n * KD))[c4] = e[c4];
    if (c4 == 0) idxf[n] = (float)id;
}

// ---------------------------------------------------------------------------
extern "C" void kernel_launch(void* const* d_in, const int* in_sizes, int n_in,
                              void* d_out, int out_size) {
    const float* z   = (const float*)d_in[0];   // (16, 256, 32, 32)
    const float* emb = (const float*)d_in[1];   // (8192, 256)
    float* out = (float*)d_out;

    float* enc   = out;                                   // encoded_flat  (N, 256)
    float* qf    = out + (size_t)N_TOTAL * KD;            // quantized_flat(N, 256)
    float* idxf  = out + (size_t)2 * N_TOTAL * KD;        // indices       (N,)
    float* quant = idxf + N_TOTAL;                        // quantized NCHW

    cudaFuncSetAttribute(argmin_wmma_kernel,
                         cudaFuncAttributeMaxDynamicSharedMemorySize, SMEM_MMA);

    reset_kernel<<<1, 32>>>();
    prep_kernel<<<KN / 8, 256>>>(emb);
    argmin_wmma_kernel<<<N_TOTAL / QT, 256, SMEM_MMA>>>(z);
    rescue_kernel<<<MAXFLAG, 256>>>(z, emb);
    // encoded_flat: per-batch plane (256 x 1024) -> (1024 x 256)
    transpose_kernel<<<dim3(HW / 32, KD / 32, BATCH), dim3(32, 8)>>>(z, enc, KD, HW);
    gather_kernel<<<N_TOTAL / 4, 256>>>(emb, qf, idxf);
    // quantized NCHW: per-batch plane (1024 x 256) -> (256 x 1024)
    transpose_kernel<<<dim3(KD / 32, HW / 32, BATCH), dim3(32, 8)>>>(qf, quant, HW, KD);
}